// round 15
// baseline (speedup 1.0000x reference)
#include <cuda_runtime.h>
#include <cstdint>

// ----------------------------------------------------------------------------
// BlockLinear via mma.sync tf32 + ldmatrix (compute_103: no tcgen05).
// out[4096, 64*256] = x-blocks @ w-blocks^T + bias
// R15: R12 + chunk-wide B-fragment prefetch, A prefetch-by-ordering, cp.async
// refill issued after the prefetch burst. CTA 128x128, 256 thr, 3-stage,
// one __syncthreads per chunk. w pre-rounded tf32(rna); x HW-truncated.
// ----------------------------------------------------------------------------

#define NBLK    64
#define INB     256
#define OUTB    256
#define BATCHSZ 4096
#define ROWF    (NBLK * INB)          // 16384
#define WELEMS  (NBLK * OUTB * INB)   // 4194304

#define MT      128
#define NT      128
#define KC      32
#define NCHUNK  (INB / KC)      // 8
#define NSTAGE  3

#define PADF    36                        // floats per smem row (144B)
#define A_BYTES (MT * PADF * 4)           // 18432
#define B_BYTES (NT * PADF * 4)           // 18432
#define STAGE_BYTES (A_BYTES + B_BYTES)   // 36864
#define SM_BIAS  0
#define SM_TILES 1024
#define SMEM_TOTAL (SM_TILES + NSTAGE * STAGE_BYTES)   // 111616 -> 2 CTAs/SM

// pre-rounded tf32 weights (static device scratch: no allocation)
__device__ float g_wtf32[WELEMS];

// ---------------- device helpers ----------------

__device__ __forceinline__ uint32_t smem_u32(const void* p) {
    uint32_t a;
    asm("{ .reg .u64 t; cvta.to.shared.u64 t, %1; cvt.u32.u64 %0, t; }" : "=r"(a) : "l"(p));
    return a;
}

__device__ __forceinline__ void cp16(uint32_t dst, const void* src) {
    asm volatile("cp.async.cg.shared.global [%0], [%1], 16;" :: "r"(dst), "l"(src));
}

__device__ __forceinline__ uint32_t f2tf32(float f) {
    uint32_t r;
    asm("cvt.rna.tf32.f32 %0, %1;" : "=r"(r) : "f"(f));
    return r;
}

// ldmatrix x4 b16: moves 4 tiles of 8 rows x 16B; per-lane address = row start.
__device__ __forceinline__ void ldsm4(uint32_t* r, uint32_t addr) {
    asm volatile("ldmatrix.sync.aligned.m8n8.x4.shared.b16 {%0,%1,%2,%3}, [%4];"
                 : "=r"(r[0]), "=r"(r[1]), "=r"(r[2]), "=r"(r[3]) : "r"(addr));
}

__device__ __forceinline__ void mma_tf32(float* c, const uint32_t* a, const uint32_t* b) {
    asm volatile(
        "mma.sync.aligned.m16n8k8.row.col.f32.tf32.tf32.f32 "
        "{%0,%1,%2,%3}, {%4,%5,%6,%7}, {%8,%9}, {%0,%1,%2,%3};"
        : "+f"(c[0]), "+f"(c[1]), "+f"(c[2]), "+f"(c[3])
        : "r"(a[0]), "r"(a[1]), "r"(a[2]), "r"(a[3]), "r"(b[0]), "r"(b[1]));
}

// ---------------- prologue: round w to tf32 (rna) ----------------

__global__ void __launch_bounds__(256)
round_w_kernel(const float4* __restrict__ w) {
    int i = blockIdx.x * blockDim.x + threadIdx.x;
    float4 v = w[i];
    float4 o;
    o.x = __uint_as_float(f2tf32(v.x));
    o.y = __uint_as_float(f2tf32(v.y));
    o.z = __uint_as_float(f2tf32(v.z));
    o.w = __uint_as_float(f2tf32(v.w));
    reinterpret_cast<float4*>(g_wtf32)[i] = o;
}

// ---------------- main kernel ----------------

__global__ void __launch_bounds__(256, 2)
blocklinear_mma_kernel(const float* __restrict__ x,
                       const float* __restrict__ bias,
                       float* __restrict__ out) {
    extern __shared__ char smem[];
    const uint32_t sbase = smem_u32(smem);
    const int tid   = threadIdx.x;
    const int bx    = blockIdx.x;        // 0..127: (blk, n-half)
    const int blk   = bx >> 1;           // weight block
    const int nth   = bx & 1;            // 128-col half of the block
    const int mtile = blockIdx.y;        // 0..31: 128-row batch slice

    if (tid < NT)
        reinterpret_cast<float*>(smem + SM_BIAS)[tid] = bias[blk * OUTB + nth * NT + tid];

    const int wid  = tid >> 5;
    const int lane = tid & 31;
    const int gID  = lane >> 2;
    const int tig  = lane & 3;
    const int wm   = wid >> 2;           // 0..1 -> 64-row strip
    const int wn   = wid & 3;            // 0..3 -> 32-col strip

    // ---- cp.async stage loader: A [128x32] from x, B [128x32] from g_wtf32 ----
    const float* wt = g_wtf32 + (size_t)blk * OUTB * INB + (size_t)nth * NT * INB;
    auto cp_stage = [&](int kc, int s) {
        const uint32_t sA = sbase + SM_TILES + s * STAGE_BYTES;
        const uint32_t sB = sA + A_BYTES;
        const int kcol = kc * KC;
#pragma unroll
        for (int it = 0; it < 4; it++) {                 // A: 1024 16B chunks
            int id = tid + it * 256;
            int row = id >> 3, c4 = id & 7;
            const float* g = x + (size_t)(mtile * MT + row) * ROWF
                               + blk * INB + kcol + c4 * 4;
            cp16(sA + row * (PADF * 4) + c4 * 16, g);
        }
#pragma unroll
        for (int it = 0; it < 4; it++) {                 // B: 1024 16B chunks
            int id = tid + it * 256;
            int row = id >> 3, c4 = id & 7;
            cp16(sB + row * (PADF * 4) + c4 * 16, wt + row * INB + kcol + c4 * 4);
        }
    };

    // prologue: NSTAGE-1 = 2 chunks in flight
#pragma unroll
    for (int s = 0; s < NSTAGE - 1; s++) {
        cp_stage(s, s);
        asm volatile("cp.async.commit_group;" ::: "memory");
    }

    float acc[4][4][4];
#pragma unroll
    for (int i = 0; i < 4; i++)
#pragma unroll
        for (int j = 0; j < 4; j++)
#pragma unroll
            for (int r = 0; r < 4; r++) acc[i][j][r] = 0.0f;

    // ldmatrix per-lane base offsets (within a stage)
    // A tiles: (m..+7,k0-3),(m+8..,k0-3),(m..,k4-7),(m+8..,k4-7)
    const uint32_t laneOffA = (uint32_t)(wm * 64 + (lane & 15)) * (PADF * 4)
                            + (uint32_t)(lane >> 4) * 16;
    // B tiles: (n..+7,k0-3),(n..+7,k4-7),(n+8..,k0-3),(n+8..,k4-7)
    const uint32_t laneOffB = (uint32_t)(wn * 32 + ((lane >> 4) & 1) * 8 + (lane & 7)) * (PADF * 4)
                            + (uint32_t)((lane >> 3) & 1) * 16;

    for (int kc = 0; kc < NCHUNK; kc++) {
        // chunk kc arrived (committed: kc+2 groups; allow 1 pending)
        asm volatile("cp.async.wait_group 1;" ::: "memory");
        __syncthreads();   // all warps done with compute(kc-1) -> slot reuse safe

        const uint32_t stg = sbase + SM_TILES + (kc % NSTAGE) * STAGE_BYTES;
        const uint32_t aB = stg + laneOffA;
        const uint32_t bB = stg + A_BYTES + laneOffB;

        // ---- chunk-wide B prefetch (8 ldsm4 -> 32 regs) + A slice0 ----
        uint32_t bfr[4][8];
        uint32_t a[4][4];
#pragma unroll
        for (int ks = 0; ks < 4; ks++) {
            ldsm4(bfr[ks] + 0, bB + ks * 32);                     // j=0,1
            ldsm4(bfr[ks] + 4, bB + 16 * (PADF * 4) + ks * 32);   // j=2,3
        }
#pragma unroll
        for (int i = 0; i < 4; i++)
            ldsm4(a[i], aB + i * 16 * (PADF * 4));                // slice 0 A

        // refill chunk kc+2 -> slot (kc+2)%3 (LDGSTS burst overlaps ldsm latency)
        if (kc + NSTAGE - 1 < NCHUNK) cp_stage(kc + NSTAGE - 1, (kc + NSTAGE - 1) % NSTAGE);
        asm volatile("cp.async.commit_group;" ::: "memory");   // uniform group count

        // ---- compute: mma(ks) then A-prefetch(ks+1) ----
#pragma unroll
        for (int ks = 0; ks < 4; ks++) {
#pragma unroll
            for (int i = 0; i < 4; i++)
#pragma unroll
                for (int j = 0; j < 4; j++)
                    mma_tf32(acc[i][j], a[i], bfr[ks] + 2 * j);
            if (ks < 3) {
#pragma unroll
                for (int i = 0; i < 4; i++)
                    ldsm4(a[i], aB + i * 16 * (PADF * 4) + (ks + 1) * 32);
            }
        }
    }

    // ---- epilogue: bias + store (float2) ----
    const float* bsm = reinterpret_cast<const float*>(smem + SM_BIAS);
#pragma unroll
    for (int i = 0; i < 4; i++) {
        const int row0 = mtile * MT + wm * 64 + i * 16 + gID;
#pragma unroll
        for (int j = 0; j < 4; j++) {
            const int colL = wn * 32 + j * 8 + tig * 2;
            const int colG = blk * OUTB + nth * NT + colL;
            float2 v0, v1;
            v0.x = acc[i][j][0] + bsm[colL];
            v0.y = acc[i][j][1] + bsm[colL + 1];
            v1.x = acc[i][j][2] + bsm[colL];
            v1.y = acc[i][j][3] + bsm[colL + 1];
            *reinterpret_cast<float2*>(out + (size_t)row0 * ROWF + colG) = v0;
            *reinterpret_cast<float2*>(out + (size_t)(row0 + 8) * ROWF + colG) = v1;
        }
    }
}

// ---------------- host ----------------

extern "C" void kernel_launch(void* const* d_in, const int* in_sizes, int n_in,
                              void* d_out, int out_size) {
    const float* x    = (const float*)d_in[0];
    const float* w    = (const float*)d_in[1];
    const float* bias = (const float*)d_in[2];
    float* out        = (float*)d_out;

    static bool attr_done = false;
    if (!attr_done) {
        cudaFuncSetAttribute(blocklinear_mma_kernel,
                             cudaFuncAttributeMaxDynamicSharedMemorySize, SMEM_TOTAL);
        attr_done = true;
    }

    // prologue: w -> tf32(rna) in g_wtf32 (16 MB, ~5us)
    round_w_kernel<<<WELEMS / 4 / 256, 256>>>(reinterpret_cast<const float4*>(w));

    dim3 grid(NBLK * 2, BATCHSZ / MT);   // (128, 32): n-halves adjacent -> x L2 dedup
    blocklinear_mma_kernel<<<grid, 256, SMEM_TOTAL>>>(x, bias, out);
}